// round 1
// baseline (speedup 1.0000x reference)
#include <cuda_runtime.h>
#include <cuda_bf16.h>

// Problem constants
#define BB 32
#define CC 64
#define TT 4096
#define NVEC ((BB * CC * TT) / 4)   // 2,097,152 float4 vectors
#define TVEC (TT / 4)               // 1024 (power of two)

#define GRID 1024
#define BLOCK 256

__device__ float g_partials[GRID];

__global__ __launch_bounds__(BLOCK) void wass_reduce_kernel(
    const float4* __restrict__ yp, const float4* __restrict__ yt)
{
    float acc = 0.0f;
    int stride = GRID * BLOCK;
    for (int v = blockIdx.x * BLOCK + threadIdx.x; v < NVEC; v += stride) {
        float4 p = yp[v];
        float4 t = yt[v];
        // t-offset of first element in this vector: 4 * (v mod TVEC)
        float w = (float)(TT - 4 * (v & (TVEC - 1)));
        float d0 = fabsf(p.x - t.x);
        float d1 = fabsf(p.y - t.y);
        float d2 = fabsf(p.z - t.z);
        float d3 = fabsf(p.w - t.w);
        acc += d0 * w + d1 * (w - 1.0f) + d2 * (w - 2.0f) + d3 * (w - 3.0f);
    }

    // Block tree reduce
    __shared__ float sdata[BLOCK];
    sdata[threadIdx.x] = acc;
    __syncthreads();
    #pragma unroll
    for (int s = BLOCK / 2; s >= 32; s >>= 1) {
        if (threadIdx.x < s) sdata[threadIdx.x] += sdata[threadIdx.x + s];
        __syncthreads();
    }
    if (threadIdx.x < 32) {
        float x = sdata[threadIdx.x];
        #pragma unroll
        for (int off = 16; off > 0; off >>= 1)
            x += __shfl_down_sync(0xFFFFFFFFu, x, off);
        if (threadIdx.x == 0) g_partials[blockIdx.x] = x;
    }
}

__global__ __launch_bounds__(BLOCK) void wass_final_kernel(float* __restrict__ out)
{
    // One block: sum GRID partials deterministically, apply scaling.
    float acc = 0.0f;
    for (int i = threadIdx.x; i < GRID; i += BLOCK)
        acc += g_partials[i];

    __shared__ float sdata[BLOCK];
    sdata[threadIdx.x] = acc;
    __syncthreads();
    #pragma unroll
    for (int s = BLOCK / 2; s >= 32; s >>= 1) {
        if (threadIdx.x < s) sdata[threadIdx.x] += sdata[threadIdx.x + s];
        __syncthreads();
    }
    if (threadIdx.x < 32) {
        float x = sdata[threadIdx.x];
        #pragma unroll
        for (int off = 16; off > 0; off >>= 1)
            x += __shfl_down_sync(0xFFFFFFFFu, x, off);
        if (threadIdx.x == 0) {
            // scaling = 2 / (T * C * (T+1)), then mean over B
            double scaling = 2.0 / ((double)TT * (double)CC * (double)(TT + 1));
            out[0] = (float)((double)x * scaling / (double)BB);
        }
    }
}

extern "C" void kernel_launch(void* const* d_in, const int* in_sizes, int n_in,
                              void* d_out, int out_size)
{
    const float4* yp = (const float4*)d_in[0];
    const float4* yt = (const float4*)d_in[1];
    float* out = (float*)d_out;

    wass_reduce_kernel<<<GRID, BLOCK>>>(yp, yt);
    wass_final_kernel<<<1, BLOCK>>>(out);
}

// round 2
// speedup vs baseline: 1.1562x; 1.1562x over previous
#include <cuda_runtime.h>
#include <cuda_bf16.h>

// Problem constants
#define BB 32
#define CC 64
#define TT 4096
#define NVEC ((BB * CC * TT) / 4)   // 2,097,152 float4 vectors
#define TVEC (TT / 4)               // 1024 (power of two)

#define GRID 1024
#define BLOCK 256
#define NWARPS (BLOCK / 32)

__device__ float g_partials[GRID];
__device__ unsigned int g_done_count = 0;   // self-resetting per launch

__device__ __forceinline__ float block_reduce(float x)
{
    __shared__ float swarp[NWARPS];
    #pragma unroll
    for (int off = 16; off > 0; off >>= 1)
        x += __shfl_down_sync(0xFFFFFFFFu, x, off);
    int lane = threadIdx.x & 31;
    int wid  = threadIdx.x >> 5;
    if (lane == 0) swarp[wid] = x;
    __syncthreads();
    if (wid == 0) {
        x = (lane < NWARPS) ? swarp[lane] : 0.0f;
        #pragma unroll
        for (int off = NWARPS / 2; off > 0; off >>= 1)
            x += __shfl_down_sync(0xFFFFFFFFu, x, off);
    }
    return x;  // valid in thread 0
}

__global__ __launch_bounds__(BLOCK) void wass_fused_kernel(
    const float4* __restrict__ yp, const float4* __restrict__ yt,
    float* __restrict__ out)
{
    float acc = 0.0f;
    const int stride = GRID * BLOCK;
    for (int v = blockIdx.x * BLOCK + threadIdx.x; v < NVEC; v += stride) {
        float4 p = yp[v];
        float4 t = yt[v];
        float w = (float)(TT - 4 * (v & (TVEC - 1)));
        float d0 = fabsf(p.x - t.x);
        float d1 = fabsf(p.y - t.y);
        float d2 = fabsf(p.z - t.z);
        float d3 = fabsf(p.w - t.w);
        acc += d0 * w + d1 * (w - 1.0f) + d2 * (w - 2.0f) + d3 * (w - 3.0f);
    }

    float bsum = block_reduce(acc);

    __shared__ bool s_is_last;
    if (threadIdx.x == 0) {
        g_partials[blockIdx.x] = bsum;
        __threadfence();                       // partial visible before counting
        unsigned int n = atomicAdd(&g_done_count, 1u);
        s_is_last = (n == GRID - 1);
        if (s_is_last) g_done_count = 0;       // reset for next graph replay
    }
    __syncthreads();

    if (s_is_last) {
        // Deterministic final reduce: fixed order over g_partials.
        float a = 0.0f;
        for (int i = threadIdx.x; i < GRID; i += BLOCK)
            a += g_partials[i];
        float total = block_reduce(a);
        if (threadIdx.x == 0) {
            double scaling = 2.0 / ((double)TT * (double)CC * (double)(TT + 1));
            out[0] = (float)((double)total * scaling / (double)BB);
        }
    }
}

extern "C" void kernel_launch(void* const* d_in, const int* in_sizes, int n_in,
                              void* d_out, int out_size)
{
    const float4* yp = (const float4*)d_in[0];
    const float4* yt = (const float4*)d_in[1];
    float* out = (float*)d_out;
    wass_fused_kernel<<<GRID, BLOCK>>>(yp, yt, out);
}

// round 5
// speedup vs baseline: 1.2832x; 1.1098x over previous
#include <cuda_runtime.h>
#include <cuda_bf16.h>

// Problem constants
#define BB 32
#define CC 64
#define TT 4096
#define NVEC ((BB * CC * TT) / 4)   // 2,097,152 float4 vectors
#define TVEC (TT / 4)               // 1024 (power of two)

#define GRID 1024
#define BLOCK 256
#define NWARPS (BLOCK / 32)
#define ITERS (NVEC / (GRID * BLOCK))   // exactly 8
#define CHUNK 4                          // float4-pairs per load batch

__device__ float g_partials[GRID];
__device__ unsigned int g_done_count = 0;   // self-resetting per launch

__device__ __forceinline__ float block_reduce(float x)
{
    __shared__ float swarp[NWARPS];
    #pragma unroll
    for (int off = 16; off > 0; off >>= 1)
        x += __shfl_down_sync(0xFFFFFFFFu, x, off);
    int lane = threadIdx.x & 31;
    int wid  = threadIdx.x >> 5;
    if (lane == 0) swarp[wid] = x;
    __syncthreads();
    if (wid == 0) {
        x = (lane < NWARPS) ? swarp[lane] : 0.0f;
        #pragma unroll
        for (int off = NWARPS / 2; off > 0; off >>= 1)
            x += __shfl_down_sync(0xFFFFFFFFu, x, off);
    }
    return x;  // valid in thread 0
}

__global__ __launch_bounds__(BLOCK) void wass_fused_kernel(
    const float4* __restrict__ yp, const float4* __restrict__ yt,
    float* __restrict__ out)
{
    const int v0 = blockIdx.x * BLOCK + threadIdx.x;
    const int S  = GRID * BLOCK;

    float acc = 0.0f;

    #pragma unroll
    for (int c = 0; c < ITERS / CHUNK; c++) {
        float4 p0, p1, p2, p3, t0, t1, t2, t3;
        const int vbase = v0 + c * CHUNK * S;

        // Front-batched loads: 8 LDG.128 in flight before any compute.
        p0 = yp[vbase + 0 * S];
        t0 = yt[vbase + 0 * S];
        p1 = yp[vbase + 1 * S];
        t1 = yt[vbase + 1 * S];
        p2 = yp[vbase + 2 * S];
        t2 = yt[vbase + 2 * S];
        p3 = yp[vbase + 3 * S];
        t3 = yt[vbase + 3 * S];

        float w0 = (float)(TT - 4 * ((vbase + 0 * S) & (TVEC - 1)));
        float w1 = (float)(TT - 4 * ((vbase + 1 * S) & (TVEC - 1)));
        float w2 = (float)(TT - 4 * ((vbase + 2 * S) & (TVEC - 1)));
        float w3 = (float)(TT - 4 * ((vbase + 3 * S) & (TVEC - 1)));

        acc += fabsf(p0.x - t0.x) * w0 + fabsf(p0.y - t0.y) * (w0 - 1.0f)
             + fabsf(p0.z - t0.z) * (w0 - 2.0f) + fabsf(p0.w - t0.w) * (w0 - 3.0f);
        acc += fabsf(p1.x - t1.x) * w1 + fabsf(p1.y - t1.y) * (w1 - 1.0f)
             + fabsf(p1.z - t1.z) * (w1 - 2.0f) + fabsf(p1.w - t1.w) * (w1 - 3.0f);
        acc += fabsf(p2.x - t2.x) * w2 + fabsf(p2.y - t2.y) * (w2 - 1.0f)
             + fabsf(p2.z - t2.z) * (w2 - 2.0f) + fabsf(p2.w - t2.w) * (w2 - 3.0f);
        acc += fabsf(p3.x - t3.x) * w3 + fabsf(p3.y - t3.y) * (w3 - 1.0f)
             + fabsf(p3.z - t3.z) * (w3 - 2.0f) + fabsf(p3.w - t3.w) * (w3 - 3.0f);
    }

    float bsum = block_reduce(acc);

    __shared__ bool s_is_last;
    if (threadIdx.x == 0) {
        g_partials[blockIdx.x] = bsum;
        __threadfence();                       // partial visible before counting
        unsigned int n = atomicAdd(&g_done_count, 1u);
        s_is_last = (n == GRID - 1);
        if (s_is_last) g_done_count = 0;       // reset for next graph replay
    }
    __syncthreads();

    if (s_is_last) {
        // Deterministic final reduce: fixed order over g_partials.
        float a = 0.0f;
        #pragma unroll 4
        for (int i = threadIdx.x; i < GRID; i += BLOCK)
            a += g_partials[i];
        float total = block_reduce(a);
        if (threadIdx.x == 0) {
            double scaling = 2.0 / ((double)TT * (double)CC * (double)(TT + 1));
            out[0] = (float)((double)total * scaling / (double)BB);
        }
    }
}

extern "C" void kernel_launch(void* const* d_in, const int* in_sizes, int n_in,
                              void* d_out, int out_size)
{
    const float4* yp = reinterpret_cast<const float4*>(d_in[0]);
    const float4* yt = reinterpret_cast<const float4*>(d_in[1]);
    float* out = reinterpret_cast<float*>(d_out);
    wass_fused_kernel<<<GRID, BLOCK>>>(yp, yt, out);
}